// round 2
// baseline (speedup 1.0000x reference)
#include <cuda_runtime.h>
#include <math.h>

#define NN 100000
#define EE 1600000
#define FIN 512
#define H1 8
#define C1 8
#define HC 64      // H1*C1
#define NC 40
#define ETOT (EE + NN)   // edges + self loops
#define NEG_SLOPE 0.2f

// ---------------- scratch (static device globals; no allocation) ----------------
__device__ float g_h1[NN * HC];     // layer-1 transformed features
__device__ float g_as1[NN * H1];    // alpha_src per node/head
__device__ float g_ad1[NN * H1];    // alpha_dst per node/head
__device__ float g_m1[NN * H1];     // segment max
__device__ float g_s1[NN * H1];     // segment sum of p
__device__ float g_o1[NN * HC];     // aggregation accumulator -> h2 (in place)
__device__ float g_z[NN * NC];      // layer-2 transformed features
__device__ float g_as2[NN];
__device__ float g_ad2[NN];
__device__ float g_m2[NN];
__device__ float g_s2[NN];
__device__ int   g_src[ETOT];
__device__ int   g_dst[ETOT];
__device__ int   g_is64;

// ---------------- helpers ----------------
__device__ __forceinline__ void atomicMaxF(float* addr, float v) {
    if (v >= 0.0f) atomicMax((int*)addr, __float_as_int(v));
    else           atomicMin((unsigned int*)addr, __float_as_uint(v));
}

__device__ __forceinline__ void redAdd4(float* p, float a, float b, float c, float d) {
    asm volatile("red.global.add.v4.f32 [%0], {%1,%2,%3,%4};"
                 :: "l"(p), "f"(a), "f"(b), "f"(c), "f"(d) : "memory");
}

__device__ __forceinline__ float lrelu(float x) {
    return x > 0.0f ? x : NEG_SLOPE * x;
}

// ---------------- init (runs every call: deterministic) ----------------
__global__ void k_init(float* __restrict__ out) {
    int i = blockIdx.x * blockDim.x + threadIdx.x;
    if (i < NN * HC) g_o1[i] = 0.0f;
    if (i < NN * H1) { g_m1[i] = -3.402823466e38f; g_s1[i] = 0.0f; }
    if (i < NN)      { g_m2[i] = -3.402823466e38f; g_s2[i] = 0.0f; }
    if (i < NN * NC) out[i] = 0.0f;
    if (i == 0)      g_is64 = 1;
}

// ---------------- edge-index dtype probe + conversion ----------------
// If delivered as int64: first 2048 int64 values are all node ids in [0,NN).
// If delivered as int32: int64 reinterpretation packs two ids -> huge values.
__global__ void k_detect(const void* __restrict__ ei) {
    int i = blockIdx.x * blockDim.x + threadIdx.x;   // 2048 threads
    const long long* p = (const long long*)ei;
    long long v = p[i];
    if (v < 0 || v >= NN) atomicAnd(&g_is64, 0);
}

__global__ void k_convert(const void* __restrict__ ei) {
    int idx = blockIdx.x * blockDim.x + threadIdx.x;
    if (idx >= ETOT) return;
    int s, d;
    if (idx < EE) {
        if (g_is64) {
            const long long* p = (const long long*)ei;
            s = (int)p[idx];
            d = (int)p[EE + idx];
        } else {
            const int* p = (const int*)ei;
            s = p[idx];
            d = p[EE + idx];
        }
    } else {
        s = d = idx - EE;
    }
    // defensive clamp: a wrong dtype guess degrades to rel_err, not a crash
    s = min(max(s, 0), NN - 1);
    d = min(max(d, 0), NN - 1);
    g_src[idx] = s;
    g_dst[idx] = d;
}

// ---------------- GEMM1: h1 = x @ W1   [NN,512]x[512,64] ----------------
__global__ void k_gemm1(const float* __restrict__ x, const float* __restrict__ W) {
    __shared__ float As[32][65];   // [k][m], padded
    __shared__ float Bs[32][64];   // [k][n]
    const int t = threadIdx.x;
    const int bm0 = blockIdx.x * 64;
    const int tx = t % 16;         // n-tile
    const int ty = t / 16;         // m-tile
    float acc[4][4] = {};

    for (int k0 = 0; k0 < FIN; k0 += 32) {
        #pragma unroll
        for (int i = 0; i < 2; i++) {
            int t4 = t * 2 + i;
            int row = t4 / 8;
            int col = (t4 % 8) * 4;
            float4 v = make_float4(0.f, 0.f, 0.f, 0.f);
            int gr = bm0 + row;
            if (gr < NN) v = *(const float4*)(x + (long)gr * FIN + k0 + col);
            As[col + 0][row] = v.x;
            As[col + 1][row] = v.y;
            As[col + 2][row] = v.z;
            As[col + 3][row] = v.w;
        }
        #pragma unroll
        for (int i = 0; i < 2; i++) {
            int t4 = t * 2 + i;
            int row = t4 / 16;
            int col = (t4 % 16) * 4;
            *(float4*)&Bs[row][col] = *(const float4*)(W + (k0 + row) * HC + col);
        }
        __syncthreads();
        #pragma unroll
        for (int k = 0; k < 32; k++) {
            float a[4], b[4];
            #pragma unroll
            for (int i = 0; i < 4; i++) a[i] = As[k][ty * 4 + i];
            #pragma unroll
            for (int j = 0; j < 4; j++) b[j] = Bs[k][tx * 4 + j];
            #pragma unroll
            for (int i = 0; i < 4; i++)
                #pragma unroll
                for (int j = 0; j < 4; j++)
                    acc[i][j] = fmaf(a[i], b[j], acc[i][j]);
        }
        __syncthreads();
    }
    #pragma unroll
    for (int i = 0; i < 4; i++) {
        int gr = bm0 + ty * 4 + i;
        if (gr < NN) {
            #pragma unroll
            for (int j = 0; j < 4; j++)
                g_h1[(long)gr * HC + tx * 4 + j] = acc[i][j];
        }
    }
}

// ---------------- per-node attention logits, layer 1 ----------------
__global__ void k_alpha1(const float* __restrict__ a_s, const float* __restrict__ a_d) {
    int i = blockIdx.x * blockDim.x + threadIdx.x;   // n*8 + h
    if (i >= NN * H1) return;
    int n = i >> 3, h = i & 7;
    const float* hp = g_h1 + (long)n * HC + h * C1;
    float s = 0.f, d = 0.f;
    #pragma unroll
    for (int c = 0; c < C1; c++) {
        float v = hp[c];
        s = fmaf(v, a_s[h * C1 + c], s);
        d = fmaf(v, a_d[h * C1 + c], d);
    }
    g_as1[i] = s;
    g_ad1[i] = d;
}

// ---------------- edge kernels, layer 1 ----------------
__global__ void k_max1() {
    int idx = blockIdx.x * blockDim.x + threadIdx.x;
    if (idx >= ETOT) return;
    int src = g_src[idx], dst = g_dst[idx];
    const float4* as = (const float4*)(g_as1 + src * H1);
    const float4* ad = (const float4*)(g_ad1 + dst * H1);
    float4 s0 = as[0], s1 = as[1], d0 = ad[0], d1 = ad[1];
    float e[H1];
    e[0] = lrelu(s0.x + d0.x); e[1] = lrelu(s0.y + d0.y);
    e[2] = lrelu(s0.z + d0.z); e[3] = lrelu(s0.w + d0.w);
    e[4] = lrelu(s1.x + d1.x); e[5] = lrelu(s1.y + d1.y);
    e[6] = lrelu(s1.z + d1.z); e[7] = lrelu(s1.w + d1.w);
    #pragma unroll
    for (int h = 0; h < H1; h++) atomicMaxF(&g_m1[dst * H1 + h], e[h]);
}

__global__ void k_agg1() {
    int idx = blockIdx.x * blockDim.x + threadIdx.x;
    if (idx >= ETOT) return;
    int src = g_src[idx], dst = g_dst[idx];
    const float4* as = (const float4*)(g_as1 + src * H1);
    const float4* ad = (const float4*)(g_ad1 + dst * H1);
    const float4* mm = (const float4*)(g_m1 + dst * H1);
    float4 s0 = as[0], s1 = as[1], d0 = ad[0], d1 = ad[1];
    float4 m0 = mm[0], m1 = mm[1];
    float p[H1];
    p[0] = __expf(lrelu(s0.x + d0.x) - m0.x);
    p[1] = __expf(lrelu(s0.y + d0.y) - m0.y);
    p[2] = __expf(lrelu(s0.z + d0.z) - m0.z);
    p[3] = __expf(lrelu(s0.w + d0.w) - m0.w);
    p[4] = __expf(lrelu(s1.x + d1.x) - m1.x);
    p[5] = __expf(lrelu(s1.y + d1.y) - m1.y);
    p[6] = __expf(lrelu(s1.z + d1.z) - m1.z);
    p[7] = __expf(lrelu(s1.w + d1.w) - m1.w);
    redAdd4(&g_s1[dst * H1 + 0], p[0], p[1], p[2], p[3]);
    redAdd4(&g_s1[dst * H1 + 4], p[4], p[5], p[6], p[7]);
    const float4* hs = (const float4*)(g_h1 + (long)src * HC);
    float* od = g_o1 + (long)dst * HC;
    #pragma unroll
    for (int h = 0; h < H1; h++) {
        float4 v0 = hs[h * 2 + 0];
        float4 v1 = hs[h * 2 + 1];
        float ph = p[h];
        redAdd4(od + h * C1 + 0, ph * v0.x, ph * v0.y, ph * v0.z, ph * v0.w);
        redAdd4(od + h * C1 + 4, ph * v1.x, ph * v1.y, ph * v1.z, ph * v1.w);
    }
}

// ---------------- normalize + bias + ELU -> h2 (in place in g_o1) ----------------
__global__ void k_norm1(const float* __restrict__ b1) {
    int i = blockIdx.x * blockDim.x + threadIdx.x;
    if (i >= NN * HC) return;
    int n = i / HC, hc = i % HC, h = hc >> 3;
    float s = g_s1[n * H1 + h] + 1e-16f;
    float v = g_o1[i] / s + b1[hc];
    g_o1[i] = v > 0.0f ? v : (expf(v) - 1.0f);   // ELU(alpha=1)
}

// ---------------- GEMM2: z = h2 @ W2   [NN,64]x[64,40] ----------------
__global__ void k_gemm2(const float* __restrict__ W2) {
    __shared__ float Ws[HC * NC];     // 2560
    __shared__ float rows[32 * HC];   // 2048
    const int t = threadIdx.x;
    const int base = blockIdx.x * 32;
    for (int i = t; i < HC * NC; i += 256) Ws[i] = W2[i];
    for (int i = t; i < 32 * HC; i += 256) {
        int r = i / HC, k = i % HC;
        int gn = base + r;
        rows[i] = (gn < NN) ? g_o1[(long)gn * HC + k] : 0.0f;
    }
    __syncthreads();
    for (int o = t; o < 32 * NC; o += 256) {
        int r = o / NC, c = o % NC;
        int gn = base + r;
        if (gn >= NN) continue;
        float acc = 0.f;
        const float* rp = rows + r * HC;
        #pragma unroll
        for (int k = 0; k < HC; k++) acc = fmaf(rp[k], Ws[k * NC + c], acc);
        g_z[(long)gn * NC + c] = acc;
    }
}

// ---------------- per-node attention logits, layer 2 ----------------
__global__ void k_alpha2(const float* __restrict__ a_s, const float* __restrict__ a_d) {
    int n = blockIdx.x * blockDim.x + threadIdx.x;
    if (n >= NN) return;
    const float* zp = g_z + (long)n * NC;
    float s = 0.f, d = 0.f;
    #pragma unroll
    for (int c = 0; c < NC; c++) {
        float v = zp[c];
        s = fmaf(v, a_s[c], s);
        d = fmaf(v, a_d[c], d);
    }
    g_as2[n] = s;
    g_ad2[n] = d;
}

// ---------------- edge kernels, layer 2 ----------------
__global__ void k_max2() {
    int idx = blockIdx.x * blockDim.x + threadIdx.x;
    if (idx >= ETOT) return;
    int src = g_src[idx], dst = g_dst[idx];
    float e = lrelu(g_as2[src] + g_ad2[dst]);
    atomicMaxF(&g_m2[dst], e);
}

__global__ void k_agg2(float* __restrict__ out) {
    int idx = blockIdx.x * blockDim.x + threadIdx.x;
    if (idx >= ETOT) return;
    int src = g_src[idx], dst = g_dst[idx];
    float e = lrelu(g_as2[src] + g_ad2[dst]);
    float p = __expf(e - g_m2[dst]);
    atomicAdd(&g_s2[dst], p);
    const float4* zs = (const float4*)(g_z + (long)src * NC);
    float* od = out + (long)dst * NC;
    #pragma unroll
    for (int q = 0; q < NC / 4; q++) {
        float4 v = zs[q];
        redAdd4(od + q * 4, p * v.x, p * v.y, p * v.z, p * v.w);
    }
}

// ---------------- final: normalize + bias + log_softmax ----------------
__global__ void k_final(float* __restrict__ out, const float* __restrict__ b2) {
    int n = blockIdx.x * blockDim.x + threadIdx.x;
    if (n >= NN) return;
    float s = g_s2[n] + 1e-16f;
    float v[NC];
    float* op = out + (long)n * NC;
    float mx = -3.402823466e38f;
    #pragma unroll
    for (int c = 0; c < NC; c++) {
        v[c] = op[c] / s + b2[c];
        mx = fmaxf(mx, v[c]);
    }
    float sum = 0.f;
    #pragma unroll
    for (int c = 0; c < NC; c++) sum += expf(v[c] - mx);
    float lse = mx + logf(sum);
    #pragma unroll
    for (int c = 0; c < NC; c++) op[c] = v[c] - lse;
}

// ---------------- launch ----------------
extern "C" void kernel_launch(void* const* d_in, const int* in_sizes, int n_in,
                              void* d_out, int out_size) {
    const float* x    = (const float*)d_in[0];
    const void*  ei   = d_in[1];
    const float* W1   = (const float*)d_in[2];
    const float* as1  = (const float*)d_in[3];
    const float* ad1  = (const float*)d_in[4];
    const float* b1   = (const float*)d_in[5];
    const float* W2   = (const float*)d_in[6];
    const float* as2  = (const float*)d_in[7];
    const float* ad2  = (const float*)d_in[8];
    const float* b2   = (const float*)d_in[9];
    float*       out  = (float*)d_out;

    const int TB = 256;
    k_init   <<<(NN * HC + TB - 1) / TB, TB>>>(out);
    k_detect <<<8, 256>>>(ei);
    k_convert<<<(ETOT + TB - 1) / TB, TB>>>(ei);
    k_gemm1  <<<(NN + 63) / 64, 256>>>(x, W1);
    k_alpha1 <<<(NN * H1 + TB - 1) / TB, TB>>>(as1, ad1);
    k_max1   <<<(ETOT + TB - 1) / TB, TB>>>();
    k_agg1   <<<(ETOT + TB - 1) / TB, TB>>>();
    k_norm1  <<<(NN * HC + TB - 1) / TB, TB>>>(b1);
    k_gemm2  <<<(NN + 31) / 32, 256>>>(W2);
    k_alpha2 <<<(NN + TB - 1) / TB, TB>>>(as2, ad2);
    k_max2   <<<(ETOT + TB - 1) / TB, TB>>>();
    k_agg2   <<<(ETOT + TB - 1) / TB, TB>>>(out);
    k_final  <<<(NN + TB - 1) / TB, TB>>>(out, b2);
}

// round 3
// speedup vs baseline: 1.8660x; 1.8660x over previous
#include <cuda_runtime.h>
#include <math.h>

#define NN 100000
#define EE 1600000
#define FIN 512
#define H1 8
#define C1 8
#define HC 64
#define NC 40
#define ETOT (EE + NN)
#define NEG_SLOPE 0.2f
#define NBLK 98   // ceil(NN/1024)

// ---------------- scratch ----------------
__device__ float g_h1[NN * HC];
__device__ float g_as1[NN * H1];
__device__ float g_ad1[NN * H1];
__device__ float g_o1[NN * HC];     // layer-1 output (post ELU) = h2
__device__ float g_z[NN * NC];
__device__ float g_as2[NN];
__device__ float g_ad2[NN];
__device__ int   g_src[ETOT];
__device__ int   g_dst[ETOT];
__device__ int   g_deg[NN];
__device__ int   g_row[NN + 1];
__device__ int   g_cursor[NN];
__device__ int   g_bsum[NBLK];
__device__ int   g_csr[ETOT];       // src ids grouped by dst
__device__ int   g_is64;

__device__ __forceinline__ float lrelu(float x) {
    return x > 0.0f ? x : NEG_SLOPE * x;
}

// ---------------- init ----------------
__global__ void k_init() {
    int i = blockIdx.x * blockDim.x + threadIdx.x;
    if (i < NN) { g_deg[i] = 0; }
    if (i == 0) g_is64 = 1;
}

// ---------------- edge dtype probe + conversion + degree count ----------------
__global__ void k_detect(const void* __restrict__ ei) {
    int i = blockIdx.x * blockDim.x + threadIdx.x;   // 2048 threads
    const long long* p = (const long long*)ei;
    long long v = p[i];
    if (v < 0 || v >= NN) atomicAnd(&g_is64, 0);
}

__global__ void k_convert(const void* __restrict__ ei) {
    int idx = blockIdx.x * blockDim.x + threadIdx.x;
    if (idx >= ETOT) return;
    int s, d;
    if (idx < EE) {
        if (g_is64) {
            const long long* p = (const long long*)ei;
            s = (int)p[idx];
            d = (int)p[EE + idx];
        } else {
            const int* p = (const int*)ei;
            s = p[idx];
            d = p[EE + idx];
        }
    } else {
        s = d = idx - EE;
    }
    s = min(max(s, 0), NN - 1);
    d = min(max(d, 0), NN - 1);
    g_src[idx] = s;
    g_dst[idx] = d;
    atomicAdd(&g_deg[d], 1);
}

// ---------------- exclusive scan of degrees (3 kernels) ----------------
__global__ void k_scan1() {
    __shared__ int sh[1024];
    int tid = threadIdx.x;
    int i = blockIdx.x * 1024 + tid;
    int v = (i < NN) ? g_deg[i] : 0;
    sh[tid] = v;
    __syncthreads();
    #pragma unroll
    for (int off = 1; off < 1024; off <<= 1) {
        int t = (tid >= off) ? sh[tid - off] : 0;
        __syncthreads();
        sh[tid] += t;
        __syncthreads();
    }
    if (i < NN) g_row[i] = sh[tid] - v;          // block-local exclusive
    if (tid == 1023) g_bsum[blockIdx.x] = sh[1023];
}

__global__ void k_scan2() {
    if (threadIdx.x == 0) {
        int acc = 0;
        for (int b = 0; b < NBLK; b++) { int t = g_bsum[b]; g_bsum[b] = acc; acc += t; }
        g_row[NN] = acc;                          // == ETOT
    }
}

__global__ void k_scan3() {
    int i = blockIdx.x * blockDim.x + threadIdx.x;
    if (i < NN) {
        int r = g_row[i] + g_bsum[i >> 10];
        g_row[i] = r;
        g_cursor[i] = r;
    }
}

__global__ void k_scatter() {
    int idx = blockIdx.x * blockDim.x + threadIdx.x;
    if (idx >= ETOT) return;
    int d = g_dst[idx];
    int pos = atomicAdd(&g_cursor[d], 1);
    g_csr[pos] = g_src[idx];
}

// ---------------- GEMM1: h1 = x @ W1   [NN,512]x[512,64], BM=128 BN=64 BK=32 ----------------
__global__ void k_gemm1(const float* __restrict__ x, const float* __restrict__ W) {
    __shared__ float As[32][132];   // [k][m], padded
    __shared__ float Bs[32][64];    // [k][n]
    const int t = threadIdx.x;
    const int bm0 = blockIdx.x * 128;
    const int tx = t % 16;          // n: 16 x 4 = 64
    const int ty = t / 16;          // m: 16 x 8 = 128
    float acc[8][4] = {};

    for (int k0 = 0; k0 < FIN; k0 += 32) {
        // A tile: 128x32 = 1024 float4, 4 per thread
        #pragma unroll
        for (int i = 0; i < 4; i++) {
            int t4 = t * 4 + i;
            int row = t4 / 8;
            int col = (t4 % 8) * 4;
            float4 v = make_float4(0.f, 0.f, 0.f, 0.f);
            int gr = bm0 + row;
            if (gr < NN) v = *(const float4*)(x + (long)gr * FIN + k0 + col);
            As[col + 0][row] = v.x;
            As[col + 1][row] = v.y;
            As[col + 2][row] = v.z;
            As[col + 3][row] = v.w;
        }
        // B tile: 32x64 = 512 float4, 2 per thread
        #pragma unroll
        for (int i = 0; i < 2; i++) {
            int t4 = t * 2 + i;
            int row = t4 / 16;
            int col = (t4 % 16) * 4;
            *(float4*)&Bs[row][col] = *(const float4*)(W + (k0 + row) * HC + col);
        }
        __syncthreads();
        #pragma unroll
        for (int k = 0; k < 32; k++) {
            float a[8], b[4];
            #pragma unroll
            for (int i = 0; i < 8; i++) a[i] = As[k][ty * 8 + i];
            #pragma unroll
            for (int j = 0; j < 4; j++) b[j] = Bs[k][tx * 4 + j];
            #pragma unroll
            for (int i = 0; i < 8; i++)
                #pragma unroll
                for (int j = 0; j < 4; j++)
                    acc[i][j] = fmaf(a[i], b[j], acc[i][j]);
        }
        __syncthreads();
    }
    #pragma unroll
    for (int i = 0; i < 8; i++) {
        int gr = bm0 + ty * 8 + i;
        if (gr < NN) {
            #pragma unroll
            for (int j = 0; j < 4; j++)
                g_h1[(long)gr * HC + tx * 4 + j] = acc[i][j];
        }
    }
}

// ---------------- per-node attention logits, layer 1 ----------------
__global__ void k_alpha1(const float* __restrict__ a_s, const float* __restrict__ a_d) {
    int i = blockIdx.x * blockDim.x + threadIdx.x;   // n*8 + h
    if (i >= NN * H1) return;
    int n = i >> 3, h = i & 7;
    const float* hp = g_h1 + (long)n * HC + h * C1;
    float s = 0.f, d = 0.f;
    #pragma unroll
    for (int c = 0; c < C1; c++) {
        float v = hp[c];
        s = fmaf(v, a_s[h * C1 + c], s);
        d = fmaf(v, a_d[h * C1 + c], d);
    }
    g_as1[i] = s;
    g_ad1[i] = d;
}

// ---------------- layer-1 CSR aggregation: warp per dst node ----------------
// lane handles channels (2*lane, 2*lane+1), head = lane/4.
// exp without max subtraction (softmax shift-invariant; |e| small here).
// Fused: normalize + bias + ELU.
__global__ void k_agg1(const float* __restrict__ b1) {
    int warp = (blockIdx.x * blockDim.x + threadIdx.x) >> 5;
    if (warp >= NN) return;
    int lane = threadIdx.x & 31;
    int n = warp;
    int h = lane >> 2;
    float adh = g_ad1[n * H1 + h];
    int beg = g_row[n], end = g_row[n + 1];
    float sum_p = 0.f, acc0 = 0.f, acc1 = 0.f;
    for (int j = beg; j < end; j++) {
        int src = g_csr[j];                       // warp-broadcast load
        float p = __expf(lrelu(g_as1[src * H1 + h] + adh));
        sum_p += p;
        float2 v = *(const float2*)(g_h1 + (long)src * HC + 2 * lane);
        acc0 = fmaf(p, v.x, acc0);
        acc1 = fmaf(p, v.y, acc1);
    }
    float inv = 1.0f / (sum_p + 1e-16f);
    float o0 = acc0 * inv + b1[2 * lane];
    float o1 = acc1 * inv + b1[2 * lane + 1];
    o0 = o0 > 0.f ? o0 : (expf(o0) - 1.f);
    o1 = o1 > 0.f ? o1 : (expf(o1) - 1.f);
    *(float2*)(g_o1 + (long)n * HC + 2 * lane) = make_float2(o0, o1);
}

// ---------------- GEMM2: z = h2 @ W2   [NN,64]x[64,40] ----------------
__global__ void k_gemm2(const float* __restrict__ W2) {
    __shared__ float Ws[HC * NC];
    __shared__ float rows[32 * HC];
    const int t = threadIdx.x;
    const int base = blockIdx.x * 32;
    for (int i = t; i < HC * NC; i += 256) Ws[i] = W2[i];
    for (int i = t; i < 32 * HC; i += 256) {
        int r = i / HC, k = i % HC;
        int gn = base + r;
        rows[i] = (gn < NN) ? g_o1[(long)gn * HC + k] : 0.0f;
    }
    __syncthreads();
    for (int o = t; o < 32 * NC; o += 256) {
        int r = o / NC, c = o % NC;
        int gn = base + r;
        if (gn >= NN) continue;
        float acc = 0.f;
        const float* rp = rows + r * HC;
        #pragma unroll
        for (int k = 0; k < HC; k++) acc = fmaf(rp[k], Ws[k * NC + c], acc);
        g_z[(long)gn * NC + c] = acc;
    }
}

// ---------------- per-node attention logits, layer 2 ----------------
__global__ void k_alpha2(const float* __restrict__ a_s, const float* __restrict__ a_d) {
    int n = blockIdx.x * blockDim.x + threadIdx.x;
    if (n >= NN) return;
    const float* zp = g_z + (long)n * NC;
    float s = 0.f, d = 0.f;
    #pragma unroll
    for (int c = 0; c < NC; c++) {
        float v = zp[c];
        s = fmaf(v, a_s[c], s);
        d = fmaf(v, a_d[c], d);
    }
    g_as2[n] = s;
    g_ad2[n] = d;
}

// ---------------- layer-2 CSR aggregation + normalize + bias + log_softmax ----------------
// warp per dst node; lane handles c=lane, plus c=32+lane for lane<8.
__global__ void k_agg2(float* __restrict__ out, const float* __restrict__ b2) {
    int warp = (blockIdx.x * blockDim.x + threadIdx.x) >> 5;
    if (warp >= NN) return;
    int lane = threadIdx.x & 31;
    int n = warp;
    float ad = g_ad2[n];
    int beg = g_row[n], end = g_row[n + 1];
    float sp = 0.f, acc_a = 0.f, acc_b = 0.f;
    for (int j = beg; j < end; j++) {
        int src = g_csr[j];
        float p = __expf(lrelu(g_as2[src] + ad));
        sp += p;
        const float* zp = g_z + (long)src * NC;
        acc_a = fmaf(p, zp[lane], acc_a);
        if (lane < 8) acc_b = fmaf(p, zp[32 + lane], acc_b);
    }
    float inv = 1.0f / (sp + 1e-16f);
    float va = acc_a * inv + b2[lane];
    float vb = (lane < 8) ? acc_b * inv + b2[32 + lane] : -3.402823466e38f;
    // log_softmax over the 40 values spread across the warp
    float m = fmaxf(va, vb);
    #pragma unroll
    for (int off = 16; off > 0; off >>= 1)
        m = fmaxf(m, __shfl_xor_sync(0xffffffffu, m, off));
    float s = expf(va - m) + ((lane < 8) ? expf(vb - m) : 0.f);
    #pragma unroll
    for (int off = 16; off > 0; off >>= 1)
        s += __shfl_xor_sync(0xffffffffu, s, off);
    float lse = m + logf(s);
    float* op = out + (long)n * NC;
    op[lane] = va - lse;
    if (lane < 8) op[32 + lane] = vb - lse;
}

// ---------------- launch ----------------
extern "C" void kernel_launch(void* const* d_in, const int* in_sizes, int n_in,
                              void* d_out, int out_size) {
    const float* x    = (const float*)d_in[0];
    const void*  ei   = d_in[1];
    const float* W1   = (const float*)d_in[2];
    const float* as1  = (const float*)d_in[3];
    const float* ad1  = (const float*)d_in[4];
    const float* b1   = (const float*)d_in[5];
    const float* W2   = (const float*)d_in[6];
    const float* as2  = (const float*)d_in[7];
    const float* ad2  = (const float*)d_in[8];
    const float* b2   = (const float*)d_in[9];
    float*       out  = (float*)d_out;

    const int TB = 256;
    k_init   <<<(NN + TB - 1) / TB, TB>>>();
    k_detect <<<8, 256>>>(ei);
    k_convert<<<(ETOT + TB - 1) / TB, TB>>>(ei);
    k_scan1  <<<NBLK, 1024>>>();
    k_scan2  <<<1, 32>>>();
    k_scan3  <<<(NN + TB - 1) / TB, TB>>>();
    k_scatter<<<(ETOT + TB - 1) / TB, TB>>>();
    k_gemm1  <<<(NN + 127) / 128, 256>>>(x, W1);
    k_alpha1 <<<(NN * H1 + TB - 1) / TB, TB>>>(as1, ad1);
    k_agg1   <<<(NN * 32 + TB - 1) / TB, TB>>>(b1);
    k_gemm2  <<<(NN + 31) / 32, 256>>>(W2);
    k_alpha2 <<<(NN + TB - 1) / TB, TB>>>(as2, ad2);
    k_agg2   <<<(NN * 32 + TB - 1) / TB, TB>>>(out, b2);
}

// round 4
// speedup vs baseline: 2.4175x; 1.2955x over previous
#include <cuda_runtime.h>
#include <cuda_bf16.h>
#include <math.h>

#define NN 100000
#define EE 1600000
#define FIN 512
#define H1 8
#define C1 8
#define HC 64
#define NC 40
#define ETOT (EE + NN)
#define NEG_SLOPE 0.2f
#define NBLK 98   // ceil(NN/1024)

// ---------------- scratch ----------------
__device__ float g_h1[NN * HC];
__device__ float g_as1[NN * H1];
__device__ float g_ad1[NN * H1];
__device__ float g_o1[NN * HC];
__device__ float g_z[NN * NC];
__device__ float g_as2[NN];
__device__ float g_ad2[NN];
__device__ int   g_src[ETOT];
__device__ int   g_dst[ETOT];
__device__ int   g_deg[NN];
__device__ int   g_row[NN + 1];
__device__ int   g_cursor[NN];
__device__ int   g_bsum[NBLK];
__device__ int   g_csr[ETOT];
__device__ int   g_is64;
__device__ unsigned short g_W1T_hi[HC * FIN];   // [n][k] bf16 hi
__device__ unsigned short g_W1T_lo[HC * FIN];   // [n][k] bf16 lo

__device__ __forceinline__ float lrelu(float x) {
    return x > 0.0f ? x : NEG_SLOPE * x;
}

__device__ __forceinline__ void split_bf16(float v, unsigned short& hi, unsigned short& lo) {
    __nv_bfloat16 h = __float2bfloat16(v);
    float r = v - __bfloat162float(h);
    __nv_bfloat16 l = __float2bfloat16(r);
    hi = __bfloat16_as_ushort(h);
    lo = __bfloat16_as_ushort(l);
}

__device__ __forceinline__ void mma_bf16(float* c, const unsigned* a, const unsigned* b) {
    asm volatile(
        "mma.sync.aligned.m16n8k16.row.col.f32.bf16.bf16.f32 "
        "{%0,%1,%2,%3},{%4,%5,%6,%7},{%8,%9},{%0,%1,%2,%3};"
        : "+f"(c[0]), "+f"(c[1]), "+f"(c[2]), "+f"(c[3])
        : "r"(a[0]), "r"(a[1]), "r"(a[2]), "r"(a[3]), "r"(b[0]), "r"(b[1]));
}

// ---------------- init ----------------
__global__ void k_init() {
    int i = blockIdx.x * blockDim.x + threadIdx.x;
    if (i < NN) g_deg[i] = 0;
    if (i == 0) g_is64 = 1;
}

// ---------------- edge dtype probe + conversion + degree count ----------------
__global__ void k_detect(const void* __restrict__ ei) {
    int i = blockIdx.x * blockDim.x + threadIdx.x;
    const long long* p = (const long long*)ei;
    long long v = p[i];
    if (v < 0 || v >= NN) atomicAnd(&g_is64, 0);
}

__global__ void k_convert(const void* __restrict__ ei) {
    int idx = blockIdx.x * blockDim.x + threadIdx.x;
    if (idx >= ETOT) return;
    int s, d;
    if (idx < EE) {
        if (g_is64) {
            const long long* p = (const long long*)ei;
            s = (int)p[idx];
            d = (int)p[EE + idx];
        } else {
            const int* p = (const int*)ei;
            s = p[idx];
            d = p[EE + idx];
        }
    } else {
        s = d = idx - EE;
    }
    s = min(max(s, 0), NN - 1);
    d = min(max(d, 0), NN - 1);
    g_src[idx] = s;
    g_dst[idx] = d;
    atomicAdd(&g_deg[d], 1);
}

// ---------------- exclusive scan of degrees ----------------
__global__ void k_scan1() {
    __shared__ int sh[1024];
    int tid = threadIdx.x;
    int i = blockIdx.x * 1024 + tid;
    int v = (i < NN) ? g_deg[i] : 0;
    sh[tid] = v;
    __syncthreads();
    #pragma unroll
    for (int off = 1; off < 1024; off <<= 1) {
        int t = (tid >= off) ? sh[tid - off] : 0;
        __syncthreads();
        sh[tid] += t;
        __syncthreads();
    }
    if (i < NN) g_row[i] = sh[tid] - v;
    if (tid == 1023) g_bsum[blockIdx.x] = sh[1023];
}

__global__ void k_scan2() {
    if (threadIdx.x == 0) {
        int acc = 0;
        for (int b = 0; b < NBLK; b++) { int t = g_bsum[b]; g_bsum[b] = acc; acc += t; }
        g_row[NN] = acc;
    }
}

__global__ void k_scan3() {
    int i = blockIdx.x * blockDim.x + threadIdx.x;
    if (i < NN) {
        int r = g_row[i] + g_bsum[i >> 10];
        g_row[i] = r;
        g_cursor[i] = r;
    }
}

__global__ void k_scatter() {
    int idx = blockIdx.x * blockDim.x + threadIdx.x;
    if (idx >= ETOT) return;
    int d = g_dst[idx];
    int pos = atomicAdd(&g_cursor[d], 1);
    g_csr[pos] = g_src[idx];
}

// ---------------- W1 split/transpose: W1[512][64] -> W1T_{hi,lo}[64][512] ----------------
__global__ void k_prepW(const float* __restrict__ W1) {
    int i = blockIdx.x * blockDim.x + threadIdx.x;
    if (i >= FIN * HC) return;
    int k = i / HC, n = i % HC;
    unsigned short hi, lo;
    split_bf16(W1[i], hi, lo);
    g_W1T_hi[n * FIN + k] = hi;
    g_W1T_lo[n * FIN + k] = lo;
}

// ---------------- GEMM1 (tensor cores, bf16x3): h1 = x @ W1 ----------------
// BM=128, BN=64, BK=32. 256 threads = 8 warps (4 m x 2 n), warp tile 32x32.
#define ASTR 40   // smem row stride in bf16 elements (80B, 16B-aligned)
__global__ __launch_bounds__(256) void k_gemm1(const float* __restrict__ x) {
    __shared__ unsigned short As_hi[128 * ASTR];
    __shared__ unsigned short As_lo[128 * ASTR];
    __shared__ unsigned short Bs_hi[64 * ASTR];
    __shared__ unsigned short Bs_lo[64 * ASTR];

    const int t = threadIdx.x;
    const int bm0 = blockIdx.x * 128;
    const int warp = t >> 5;
    const int lane = t & 31;
    const int g = lane >> 2;       // 0..7
    const int q = lane & 3;        // 0..3
    const int warp_m = warp >> 1;  // 0..3
    const int warp_n = warp & 1;   // 0..1

    float acc[2][4][4];
    #pragma unroll
    for (int i = 0; i < 2; i++)
        #pragma unroll
        for (int j = 0; j < 4; j++)
            #pragma unroll
            for (int r = 0; r < 4; r++) acc[i][j][r] = 0.f;

    for (int k0 = 0; k0 < FIN; k0 += 32) {
        // ---- load A tile 128x32 fp32, split to bf16 hi/lo ----
        #pragma unroll
        for (int i = 0; i < 4; i++) {
            int idx = i * 256 + t;            // float4 index, 1024 total
            int row = idx >> 3;
            int col = (idx & 7) * 4;
            float4 v = make_float4(0.f, 0.f, 0.f, 0.f);
            int gr = bm0 + row;
            if (gr < NN) v = *(const float4*)(x + (long)gr * FIN + k0 + col);
            unsigned short h0, l0, h1_, l1_, h2, l2, h3, l3;
            split_bf16(v.x, h0, l0);
            split_bf16(v.y, h1_, l1_);
            split_bf16(v.z, h2, l2);
            split_bf16(v.w, h3, l3);
            unsigned* ph = (unsigned*)&As_hi[row * ASTR + col];
            unsigned* pl = (unsigned*)&As_lo[row * ASTR + col];
            ph[0] = (unsigned)h0 | ((unsigned)h1_ << 16);
            ph[1] = (unsigned)h2 | ((unsigned)h3 << 16);
            pl[0] = (unsigned)l0 | ((unsigned)l1_ << 16);
            pl[1] = (unsigned)l2 | ((unsigned)l3 << 16);
        }
        // ---- load B tile: W1T[64][512] rows n, cols k0..k0+31 ----
        {
            int row = t >> 2;                 // 0..63
            int seg = t & 3;                  // 8 bf16 each
            uint4 vh = *(const uint4*)&g_W1T_hi[row * FIN + k0 + seg * 8];
            uint4 vl = *(const uint4*)&g_W1T_lo[row * FIN + k0 + seg * 8];
            *(uint4*)&Bs_hi[row * ASTR + seg * 8] = vh;
            *(uint4*)&Bs_lo[row * ASTR + seg * 8] = vl;
        }
        __syncthreads();

        #pragma unroll
        for (int ka = 0; ka < 2; ka++) {
            const int kc = ka * 16;
            unsigned a_hi[2][4], a_lo[2][4], b_hi[4][2], b_lo[4][2];
            #pragma unroll
            for (int ma = 0; ma < 2; ma++) {
                int r0 = warp_m * 32 + ma * 16;
                a_hi[ma][0] = *(const unsigned*)&As_hi[(r0 + g) * ASTR + kc + 2 * q];
                a_hi[ma][1] = *(const unsigned*)&As_hi[(r0 + g + 8) * ASTR + kc + 2 * q];
                a_hi[ma][2] = *(const unsigned*)&As_hi[(r0 + g) * ASTR + kc + 2 * q + 8];
                a_hi[ma][3] = *(const unsigned*)&As_hi[(r0 + g + 8) * ASTR + kc + 2 * q + 8];
                a_lo[ma][0] = *(const unsigned*)&As_lo[(r0 + g) * ASTR + kc + 2 * q];
                a_lo[ma][1] = *(const unsigned*)&As_lo[(r0 + g + 8) * ASTR + kc + 2 * q];
                a_lo[ma][2] = *(const unsigned*)&As_lo[(r0 + g) * ASTR + kc + 2 * q + 8];
                a_lo[ma][3] = *(const unsigned*)&As_lo[(r0 + g + 8) * ASTR + kc + 2 * q + 8];
            }
            #pragma unroll
            for (int na = 0; na < 4; na++) {
                int n0 = warp_n * 32 + na * 8;
                b_hi[na][0] = *(const unsigned*)&Bs_hi[(n0 + g) * ASTR + kc + 2 * q];
                b_hi[na][1] = *(const unsigned*)&Bs_hi[(n0 + g) * ASTR + kc + 2 * q + 8];
                b_lo[na][0] = *(const unsigned*)&Bs_lo[(n0 + g) * ASTR + kc + 2 * q];
                b_lo[na][1] = *(const unsigned*)&Bs_lo[(n0 + g) * ASTR + kc + 2 * q + 8];
            }
            #pragma unroll
            for (int ma = 0; ma < 2; ma++)
                #pragma unroll
                for (int na = 0; na < 4; na++) {
                    mma_bf16(acc[ma][na], a_hi[ma], b_hi[na]);
                    mma_bf16(acc[ma][na], a_hi[ma], b_lo[na]);
                    mma_bf16(acc[ma][na], a_lo[ma], b_hi[na]);
                }
        }
        __syncthreads();
    }

    // ---- epilogue: write h1 ----
    #pragma unroll
    for (int ma = 0; ma < 2; ma++) {
        int r0 = bm0 + warp_m * 32 + ma * 16 + g;
        #pragma unroll
        for (int na = 0; na < 4; na++) {
            int c = warp_n * 32 + na * 8 + 2 * q;
            if (r0 < NN)
                *(float2*)(g_h1 + (long)r0 * HC + c) = make_float2(acc[ma][na][0], acc[ma][na][1]);
            if (r0 + 8 < NN)
                *(float2*)(g_h1 + (long)(r0 + 8) * HC + c) = make_float2(acc[ma][na][2], acc[ma][na][3]);
        }
    }
}

// ---------------- per-node attention logits, layer 1 ----------------
__global__ void k_alpha1(const float* __restrict__ a_s, const float* __restrict__ a_d) {
    int i = blockIdx.x * blockDim.x + threadIdx.x;
    if (i >= NN * H1) return;
    int n = i >> 3, h = i & 7;
    const float* hp = g_h1 + (long)n * HC + h * C1;
    float s = 0.f, d = 0.f;
    #pragma unroll
    for (int c = 0; c < C1; c++) {
        float v = hp[c];
        s = fmaf(v, a_s[h * C1 + c], s);
        d = fmaf(v, a_d[h * C1 + c], d);
    }
    g_as1[i] = s;
    g_ad1[i] = d;
}

// ---------------- layer-1 CSR aggregation: warp per dst node ----------------
__global__ void k_agg1(const float* __restrict__ b1) {
    int warp = (blockIdx.x * blockDim.x + threadIdx.x) >> 5;
    if (warp >= NN) return;
    int lane = threadIdx.x & 31;
    int n = warp;
    int h = lane >> 2;
    float adh = g_ad1[n * H1 + h];
    int beg = g_row[n], end = g_row[n + 1];
    float sum_p = 0.f, acc0 = 0.f, acc1 = 0.f;
    for (int j = beg; j < end; j++) {
        int src = g_csr[j];
        float p = __expf(lrelu(g_as1[src * H1 + h] + adh));
        sum_p += p;
        float2 v = *(const float2*)(g_h1 + (long)src * HC + 2 * lane);
        acc0 = fmaf(p, v.x, acc0);
        acc1 = fmaf(p, v.y, acc1);
    }
    float inv = 1.0f / (sum_p + 1e-16f);
    float o0 = acc0 * inv + b1[2 * lane];
    float o1 = acc1 * inv + b1[2 * lane + 1];
    o0 = o0 > 0.f ? o0 : (expf(o0) - 1.f);
    o1 = o1 > 0.f ? o1 : (expf(o1) - 1.f);
    *(float2*)(g_o1 + (long)n * HC + 2 * lane) = make_float2(o0, o1);
}

// ---------------- GEMM2: z = h2 @ W2   [NN,64]x[64,40] ----------------
__global__ void k_gemm2(const float* __restrict__ W2) {
    __shared__ float Ws[HC * NC];
    __shared__ float rows[32 * HC];
    const int t = threadIdx.x;
    const int base = blockIdx.x * 32;
    for (int i = t; i < HC * NC; i += 256) Ws[i] = W2[i];
    for (int i = t; i < 32 * HC; i += 256) {
        int r = i / HC, k = i % HC;
        int gn = base + r;
        rows[i] = (gn < NN) ? g_o1[(long)gn * HC + k] : 0.0f;
    }
    __syncthreads();
    for (int o = t; o < 32 * NC; o += 256) {
        int r = o / NC, c = o % NC;
        int gn = base + r;
        if (gn >= NN) continue;
        float acc = 0.f;
        const float* rp = rows + r * HC;
        #pragma unroll
        for (int k = 0; k < HC; k++) acc = fmaf(rp[k], Ws[k * NC + c], acc);
        g_z[(long)gn * NC + c] = acc;
    }
}

// ---------------- per-node attention logits, layer 2 ----------------
__global__ void k_alpha2(const float* __restrict__ a_s, const float* __restrict__ a_d) {
    int n = blockIdx.x * blockDim.x + threadIdx.x;
    if (n >= NN) return;
    const float* zp = g_z + (long)n * NC;
    float s = 0.f, d = 0.f;
    #pragma unroll
    for (int c = 0; c < NC; c++) {
        float v = zp[c];
        s = fmaf(v, a_s[c], s);
        d = fmaf(v, a_d[c], d);
    }
    g_as2[n] = s;
    g_ad2[n] = d;
}

// ---------------- layer-2 CSR aggregation + log_softmax ----------------
__global__ void k_agg2(float* __restrict__ out, const float* __restrict__ b2) {
    int warp = (blockIdx.x * blockDim.x + threadIdx.x) >> 5;
    if (warp >= NN) return;
    int lane = threadIdx.x & 31;
    int n = warp;
    float ad = g_ad2[n];
    int beg = g_row[n], end = g_row[n + 1];
    float sp = 0.f, acc_a = 0.f, acc_b = 0.f;
    for (int j = beg; j < end; j++) {
        int src = g_csr[j];
        float p = __expf(lrelu(g_as2[src] + ad));
        sp += p;
        const float* zp = g_z + (long)src * NC;
        acc_a = fmaf(p, zp[lane], acc_a);
        if (lane < 8) acc_b = fmaf(p, zp[32 + lane], acc_b);
    }
    float inv = 1.0f / (sp + 1e-16f);
    float va = acc_a * inv + b2[lane];
    float vb = (lane < 8) ? acc_b * inv + b2[32 + lane] : -3.402823466e38f;
    float m = fmaxf(va, vb);
    #pragma unroll
    for (int off = 16; off > 0; off >>= 1)
        m = fmaxf(m, __shfl_xor_sync(0xffffffffu, m, off));
    float s = expf(va - m) + ((lane < 8) ? expf(vb - m) : 0.f);
    #pragma unroll
    for (int off = 16; off > 0; off >>= 1)
        s += __shfl_xor_sync(0xffffffffu, s, off);
    float lse = m + logf(s);
    float* op = out + (long)n * NC;
    op[lane] = va - lse;
    if (lane < 8) op[32 + lane] = vb - lse;
}

// ---------------- launch ----------------
extern "C" void kernel_launch(void* const* d_in, const int* in_sizes, int n_in,
                              void* d_out, int out_size) {
    const float* x    = (const float*)d_in[0];
    const void*  ei   = d_in[1];
    const float* W1   = (const float*)d_in[2];
    const float* as1  = (const float*)d_in[3];
    const float* ad1  = (const float*)d_in[4];
    const float* b1   = (const float*)d_in[5];
    const float* W2   = (const float*)d_in[6];
    const float* as2  = (const float*)d_in[7];
    const float* ad2  = (const float*)d_in[8];
    const float* b2   = (const float*)d_in[9];
    float*       out  = (float*)d_out;

    const int TB = 256;
    k_init   <<<(NN + TB - 1) / TB, TB>>>();
    k_detect <<<8, 256>>>(ei);
    k_convert<<<(ETOT + TB - 1) / TB, TB>>>(ei);
    k_prepW  <<<(FIN * HC + TB - 1) / TB, TB>>>(W1);
    k_scan1  <<<NBLK, 1024>>>();
    k_scan2  <<<1, 32>>>();
    k_scan3  <<<(NN + TB - 1) / TB, TB>>>();
    k_scatter<<<(ETOT + TB - 1) / TB, TB>>>();
    k_gemm1  <<<(NN + 127) / 128, 256>>>(x);
    k_alpha1 <<<(NN * H1 + TB - 1) / TB, TB>>>(as1, ad1);
    k_agg1   <<<(NN * 32 + TB - 1) / TB, TB>>>(b1);
    k_gemm2  <<<(NN + 31) / 32, 256>>>(W2);
    k_alpha2 <<<(NN + TB - 1) / TB, TB>>>(as2, ad2);
    k_agg2   <<<(NN * 32 + TB - 1) / TB, TB>>>(out, b2);
}